// round 5
// baseline (speedup 1.0000x reference)
#include <cuda_runtime.h>
#include <cstdint>

#define BB 8
#define CC 1024
#define HWD 4096
#define KK 64
#define PP (BB*HWD)   // 32768 pixels

// ---------------- scratch (device globals; no allocation allowed) ----------------
__device__ float g_gnT[CC*KK];               // normalized centroids, transposed [c][k]
__device__ int   g_idx[PP];                  // argmax centroid per pixel
__device__ float g_cnt[BB*KK];               // per-batch cluster counts
__device__ float g_cl[BB*KK*CC];             // local centroids (sum then divided in place)
__device__ float g_w[PP];                    // calibration weight per pixel
__device__ float g_xcal[(size_t)BB*CC*HWD];  // calibrated activations (134 MB)

// ---------------- packed f32x2 helpers ----------------
__device__ __forceinline__ void ffma2(unsigned long long &acc, unsigned long long a, unsigned long long b){
    asm("fma.rn.f32x2 %0, %1, %2, %0;" : "+l"(acc) : "l"(a), "l"(b));
}
__device__ __forceinline__ unsigned long long dup2(float v){
    unsigned long long r; unsigned int u = __float_as_uint(v);
    asm("mov.b64 %0, {%1, %1};" : "=l"(r) : "r"(u));
    return r;
}
__device__ __forceinline__ float2 unpack2(unsigned long long v){
    unsigned int lo, hi;
    asm("mov.b64 {%0, %1}, %2;" : "=r"(lo), "=r"(hi) : "l"(v));
    return make_float2(__uint_as_float(lo), __uint_as_float(hi));
}

// ---------------- K1: normalize centroids, store transposed [c][k] ----------------
__global__ void knorm(const float* __restrict__ cen){
    int k = blockIdx.x;
    __shared__ float red[256];
    float s = 0.f;
    for(int c = threadIdx.x; c < CC; c += 256){ float v = cen[k*CC+c]; s += v*v; }
    red[threadIdx.x] = s; __syncthreads();
    for(int o = 128; o > 0; o >>= 1){
        if(threadIdx.x < o) red[threadIdx.x] += red[threadIdx.x + o];
        __syncthreads();
    }
    float inv = 1.0f / fmaxf(sqrtf(red[0]), 1e-12f);
    for(int c = threadIdx.x; c < CC; c += 256) g_gnT[c*KK + k] = cen[k*CC+c] * inv;
}

// ---------------- K2: nearest-centroid assignment (argmax of x . g_n) ----------------
// argmax_k (x.g_k)/||x|| == argmax_k x.g_k  (||x|| > 0 per-pixel scale), so x is
// never normalized. sims layout: sims[i] packs centroids (2i, 2i+1); ascending
// scan with strict '>' reproduces argmax first-max tie-breaking.
__global__ __launch_bounds__(256) void kassign(const float* __restrict__ x){
    int p  = blockIdx.x*256 + threadIdx.x;
    int b  = p >> 12, hw = p & 4095;
    const float* xb = x + (size_t)b*CC*HWD + hw;
    __shared__ ulonglong2 sg[1024];           // 64 channels x 64 k  (16 KB)
    unsigned long long sims[32];
    #pragma unroll
    for(int i = 0; i < 32; i++) sims[i] = 0ull;

    for(int c0 = 0; c0 < CC; c0 += 64){
        __syncthreads();
        const float4* src = (const float4*)(g_gnT + c0*KK);
        #pragma unroll
        for(int l = 0; l < 4; l++)
            ((float4*)sg)[threadIdx.x + l*256] = src[threadIdx.x + l*256];
        __syncthreads();
        #pragma unroll 8
        for(int ci = 0; ci < 64; ci++){
            float xv = xb[(size_t)(c0+ci)*HWD];
            unsigned long long xd = dup2(xv);
            const ulonglong2* row = &sg[ci*16];
            #pragma unroll
            for(int j = 0; j < 16; j++){
                ulonglong2 g = row[j];
                ffma2(sims[2*j],   xd, g.x);
                ffma2(sims[2*j+1], xd, g.y);
            }
        }
    }
    float best = -1e30f; int bi = 0;
    #pragma unroll
    for(int i = 0; i < 32; i++){
        float2 v = unpack2(sims[i]);
        if(v.x > best){ best = v.x; bi = 2*i;   }
        if(v.y > best){ best = v.y; bi = 2*i+1; }
    }
    g_idx[p] = bi;
}

// ---------------- K3: per-batch cluster histogram ----------------
__global__ void khist(){
    __shared__ int cnt[KK];
    if(threadIdx.x < KK) cnt[threadIdx.x] = 0;
    __syncthreads();
    int b = blockIdx.x;
    for(int p = threadIdx.x; p < HWD; p += 256) atomicAdd(&cnt[g_idx[b*HWD + p]], 1);
    __syncthreads();
    if(threadIdx.x < KK) g_cnt[b*KK + threadIdx.x] = (float)cnt[threadIdx.x];
}

// ---------------- K4: per-batch cluster sums (shared-memory scatter) ----------------
__global__ __launch_bounds__(256) void ksum(const float* __restrict__ x){
    int b = blockIdx.y, c0 = blockIdx.x*64;
    __shared__ float acc[KK][65];             // padded vs bank conflicts (16.6 KB)
    __shared__ int sidx[HWD];                 // 16 KB
    for(int i = threadIdx.x; i < KK*65; i += 256) (&acc[0][0])[i] = 0.f;
    for(int i = threadIdx.x; i < HWD;   i += 256) sidx[i] = g_idx[b*HWD + i];
    __syncthreads();
    int pi = threadIdx.x & 63;                // 64 consecutive pixels -> coalesced
    int c4 = threadIdx.x >> 6;                // 4 channels at a time
    for(int cc = 0; cc < 64; cc += 4){
        int c = c0 + cc + c4;
        const float* xr = x + ((size_t)b*CC + c)*HWD;
        for(int p0 = 0; p0 < HWD; p0 += 64){
            int p = p0 + pi;
            atomicAdd(&acc[sidx[p]][cc + c4], xr[p]);
        }
    }
    __syncthreads();
    for(int i = threadIdx.x; i < KK*64; i += 256){
        int k = i >> 6, c = i & 63;
        g_cl[((size_t)b*KK + k)*CC + c0 + c] = acc[k][c];   // full overwrite: replay-safe
    }
}

// ---------------- K5: divide sums by max(count, 1) in place ----------------
__global__ void kdiv(){
    int bk = blockIdx.x;
    float cnt = fmaxf(g_cnt[bk], 1.0f);
    float inv = 1.0f / cnt;
    for(int c = threadIdx.x; c < CC; c += 256)
        g_cl[(size_t)bk*CC + c] *= inv;
}

// ---------------- K6: calibration weight w = exp(-mean_c (cl-x)^2) ----------------
__global__ __launch_bounds__(256) void kw(const float* __restrict__ x){
    int b = blockIdx.y;
    int p = blockIdx.x*256 + threadIdx.x;     // pixel within batch
    int k = g_idx[b*HWD + p];
    __shared__ float scl[KK][65];             // 16.6 KB chunk of local centroids
    const float* xb = x + (size_t)b*CC*HWD + p;
    float ssd = 0.f;
    for(int c0 = 0; c0 < CC; c0 += 64){
        __syncthreads();
        for(int i = threadIdx.x; i < KK*64; i += 256){
            int kk = i >> 6, ci = i & 63;
            scl[kk][ci] = g_cl[((size_t)b*KK + kk)*CC + c0 + ci];
        }
        __syncthreads();
        #pragma unroll 8
        for(int ci = 0; ci < 64; ci++){
            float d = scl[k][ci] - xb[(size_t)(c0+ci)*HWD];
            ssd += d*d;
        }
    }
    g_w[b*HWD + p] = expf(-ssd * (1.0f/1024.0f));
}

// ---------------- K7: x_cal = x + w*(cl - x) ----------------
__global__ void kxcal(const float* __restrict__ x){
    int e  = blockIdx.x*256 + threadIdx.x;    // element index in [B,C,H,W]
    int b  = e >> 22;
    int c  = (e >> 12) & 1023;
    int hw = e & 4095;
    int pidx = (b << 12) + hw;
    float xv  = x[e];
    int   k   = g_idx[pidx];
    float wv  = g_w[pidx];
    float clv = g_cl[((size_t)b*KK + k)*CC + c];
    g_xcal[e] = xv + wv*(clv - xv);
}

// ---------------- K8: 1x1 conv GEMM + bias + relu (packed f32x2 FMA) ----------------
// 128x128 tile per CTA, 8x8 micro-tile per thread, double-buffered smem.
__global__ __launch_bounds__(256,2) void kgemm(const float* __restrict__ Wt,
                                               const float* __restrict__ bias,
                                               float* __restrict__ out){
    const int bxp = blockIdx.x;   // pixel tile (32 of 128)
    const int byo = blockIdx.y;   // out-channel tile (8 of 128)
    const int b   = blockIdx.z;
    __shared__ float sW[16][128]; // [kk][o]
    __shared__ float sX[16][128]; // [kk][p]
    const int tid = threadIdx.x;
    const int tx = tid & 15, ty = tid >> 4;

    const float* Xb = g_xcal + (size_t)b*CC*HWD + bxp*128;
    const float* Wb = Wt + (size_t)byo*128*CC;

    unsigned long long acc[8][4];
    #pragma unroll
    for(int i = 0; i < 8; i++)
        #pragma unroll
        for(int j = 0; j < 4; j++) acc[i][j] = 0ull;

    float4 wreg[2], xreg[2];
    // prefetch chunk 0
    #pragma unroll
    for(int l = 0; l < 2; l++){
        int j = tid + l*256;
        int row = j >> 2, cc = (j & 3)*4;
        wreg[l] = *(const float4*)&Wb[(size_t)row*CC + cc];
        int kk = j >> 5, pq = (j & 31)*4;
        xreg[l] = *(const float4*)&Xb[(size_t)kk*HWD + pq];
    }

    for(int c0 = 0; c0 < CC; c0 += 16){
        __syncthreads();
        #pragma unroll
        for(int l = 0; l < 2; l++){
            int j = tid + l*256;
            int row = j >> 2, cc = (j & 3)*4;
            sW[cc+0][row] = wreg[l].x; sW[cc+1][row] = wreg[l].y;
            sW[cc+2][row] = wreg[l].z; sW[cc+3][row] = wreg[l].w;
            int kk = j >> 5, pq = (j & 31)*4;
            *(float4*)&sX[kk][pq] = xreg[l];
        }
        __syncthreads();
        if(c0 + 16 < CC){
            #pragma unroll
            for(int l = 0; l < 2; l++){
                int j = tid + l*256;
                int row = j >> 2, cc = (j & 3)*4;
                wreg[l] = *(const float4*)&Wb[(size_t)row*CC + c0 + 16 + cc];
                int kk = j >> 5, pq = (j & 31)*4;
                xreg[l] = *(const float4*)&Xb[(size_t)(c0 + 16 + kk)*HWD + pq];
            }
        }
        #pragma unroll
        for(int kk = 0; kk < 16; kk++){
            float4 a0 = *(const float4*)&sW[kk][ty*8];
            float4 a1 = *(const float4*)&sW[kk][ty*8 + 4];
            ulonglong2 b01 = *(const ulonglong2*)&sX[kk][tx*8];
            ulonglong2 b23 = *(const ulonglong2*)&sX[kk][tx*8 + 4];
            float av[8] = {a0.x,a0.y,a0.z,a0.w,a1.x,a1.y,a1.z,a1.w};
            #pragma unroll
            for(int oi = 0; oi < 8; oi++){
                unsigned long long ad = dup2(av[oi]);
                ffma2(acc[oi][0], ad, b01.x);
                ffma2(acc[oi][1], ad, b01.y);
                ffma2(acc[oi][2], ad, b23.x);
                ffma2(acc[oi][3], ad, b23.y);
            }
        }
    }

    // epilogue: + bias, relu, store
    #pragma unroll
    for(int oi = 0; oi < 8; oi++){
        int o = byo*128 + ty*8 + oi;
        float bv = bias[o];
        float res[8];
        #pragma unroll
        for(int j = 0; j < 4; j++){
            float2 v = unpack2(acc[oi][j]);
            res[2*j]   = fmaxf(v.x + bv, 0.f);
            res[2*j+1] = fmaxf(v.y + bv, 0.f);
        }
        float* op = out + (size_t)b*CC*HWD + (size_t)o*HWD + bxp*128 + tx*8;
        *(float4*)op     = make_float4(res[0],res[1],res[2],res[3]);
        *(float4*)(op+4) = make_float4(res[4],res[5],res[6],res[7]);
    }
}

// ---------------- launch ----------------
extern "C" void kernel_launch(void* const* d_in, const int* in_sizes, int n_in,
                              void* d_out, int out_size){
    const float* x   = (const float*)d_in[0];
    const float* cen = (const float*)d_in[1];
    const float* fw  = (const float*)d_in[2];
    const float* fb  = (const float*)d_in[3];
    float* out = (float*)d_out;

    knorm  <<<KK, 256>>>(cen);
    kassign<<<PP/256, 256>>>(x);
    khist  <<<BB, 256>>>();
    ksum   <<<dim3(16, BB), 256>>>(x);
    kdiv   <<<BB*KK, 256>>>();
    kw     <<<dim3(HWD/256, BB), 256>>>(x);
    kxcal  <<<(int)(((size_t)BB*CC*HWD)/256), 256>>>(x);
    kgemm  <<<dim3(32, 8, BB), 256>>>(fw, fb, out);
}

// round 7
// speedup vs baseline: 1.0670x; 1.0670x over previous
#include <cuda_runtime.h>
#include <cstdint>

#define BB 8
#define CC 1024
#define HWD 4096
#define KK 64
#define PP (BB*HWD)   // 32768 pixels

// ---------------- scratch (device globals; no allocation allowed) ----------------
__device__ float    g_gnT[CC*KK];               // normalized centroids, transposed [c][k]
__device__ int      g_idx[PP];                  // argmax centroid per pixel
__device__ float    g_cnt[BB*KK];               // per-batch cluster counts (float, for kdiv)
__device__ int      g_icnt[BB*KK];              // per-batch cluster counts (int, for scan)
__device__ int      g_off[BB*KK];               // exclusive prefix offsets
__device__ int      g_cur[BB*KK];               // scatter cursors (re-init by kscan each run)
__device__ uint16_t g_sp[PP];                   // pixel ids sorted by cluster, per batch
__device__ uint8_t  g_sk[PP];                   // cluster id per sorted position
__device__ float    g_cl[BB*KK*CC];             // local centroids (zeroed, summed, divided)
__device__ float    g_w[PP];                    // calibration weight per pixel
__device__ float    g_xcal[(size_t)BB*CC*HWD];  // calibrated activations (134 MB)

// ---------------- packed f32x2 helpers ----------------
__device__ __forceinline__ void ffma2(unsigned long long &acc, unsigned long long a, unsigned long long b){
    asm("fma.rn.f32x2 %0, %1, %2, %0;" : "+l"(acc) : "l"(a), "l"(b));
}
__device__ __forceinline__ unsigned long long dup2(float v){
    unsigned long long r; unsigned int u = __float_as_uint(v);
    asm("mov.b64 %0, {%1, %1};" : "=l"(r) : "r"(u));
    return r;
}
__device__ __forceinline__ float2 unpack2(unsigned long long v){
    unsigned int lo, hi;
    asm("mov.b64 {%0, %1}, %2;" : "=r"(lo), "=r"(hi) : "l"(v));
    return make_float2(__uint_as_float(lo), __uint_as_float(hi));
}

// ---------------- K1: normalize centroids, store transposed [c][k] ----------------
__global__ void knorm(const float* __restrict__ cen){
    int k = blockIdx.x;
    __shared__ float red[256];
    float s = 0.f;
    for(int c = threadIdx.x; c < CC; c += 256){ float v = cen[k*CC+c]; s += v*v; }
    red[threadIdx.x] = s; __syncthreads();
    for(int o = 128; o > 0; o >>= 1){
        if(threadIdx.x < o) red[threadIdx.x] += red[threadIdx.x + o];
        __syncthreads();
    }
    float inv = 1.0f / fmaxf(sqrtf(red[0]), 1e-12f);
    for(int c = threadIdx.x; c < CC; c += 256) g_gnT[c*KK + k] = cen[k*CC+c] * inv;
}

// ---------------- K2: nearest-centroid assignment (argmax of x . g_n) ----------------
// argmax_k (x.g_k)/||x|| == argmax_k x.g_k (||x||>0 scale). Ascending scan with
// strict '>' matches argmax first-max tie-breaking.
__global__ __launch_bounds__(256) void kassign(const float* __restrict__ x){
    int p  = blockIdx.x*256 + threadIdx.x;
    int b  = p >> 12, hw = p & 4095;
    const float* xb = x + (size_t)b*CC*HWD + hw;
    __shared__ ulonglong2 sg[1024];           // 64 channels x 64 k  (16 KB)
    unsigned long long sims[32];
    #pragma unroll
    for(int i = 0; i < 32; i++) sims[i] = 0ull;

    for(int c0 = 0; c0 < CC; c0 += 64){
        __syncthreads();
        const float4* src = (const float4*)(g_gnT + c0*KK);
        #pragma unroll
        for(int l = 0; l < 4; l++)
            ((float4*)sg)[threadIdx.x + l*256] = src[threadIdx.x + l*256];
        __syncthreads();
        #pragma unroll 8
        for(int ci = 0; ci < 64; ci++){
            float xv = xb[(size_t)(c0+ci)*HWD];
            unsigned long long xd = dup2(xv);
            const ulonglong2* row = &sg[ci*16];
            #pragma unroll
            for(int j = 0; j < 16; j++){
                ulonglong2 g = row[j];
                ffma2(sims[2*j],   xd, g.x);
                ffma2(sims[2*j+1], xd, g.y);
            }
        }
    }
    float best = -1e30f; int bi = 0;
    #pragma unroll
    for(int i = 0; i < 32; i++){
        float2 v = unpack2(sims[i]);
        if(v.x > best){ best = v.x; bi = 2*i;   }
        if(v.y > best){ best = v.y; bi = 2*i+1; }
    }
    g_idx[p] = bi;
}

// ---------------- K3: per-batch cluster histogram ----------------
__global__ void khist(){
    __shared__ int cnt[KK];
    if(threadIdx.x < KK) cnt[threadIdx.x] = 0;
    __syncthreads();
    int b = blockIdx.x;
    for(int p = threadIdx.x; p < HWD; p += 256) atomicAdd(&cnt[g_idx[b*HWD + p]], 1);
    __syncthreads();
    if(threadIdx.x < KK){
        g_cnt [b*KK + threadIdx.x] = (float)cnt[threadIdx.x];
        g_icnt[b*KK + threadIdx.x] = cnt[threadIdx.x];
    }
}

// ---------------- K3b: exclusive scan of counts -> offsets + cursors ----------------
__global__ void kscan(){
    int b = blockIdx.x, t = threadIdx.x;      // 8 blocks x 64 threads
    __shared__ int s[KK];
    s[t] = g_icnt[b*KK + t];
    __syncthreads();
    if(t == 0){
        int acc = 0;
        for(int k = 0; k < KK; k++){ int c = s[k]; s[k] = acc; acc += c; }
    }
    __syncthreads();
    g_off[b*KK + t] = s[t];
    g_cur[b*KK + t] = s[t];                   // re-initialized every replay
}

// ---------------- K3c: counting-sort scatter (pixel ids by cluster) ----------------
__global__ void kscatter(){
    int p  = blockIdx.x*256 + threadIdx.x;
    int b  = p >> 12, hw = p & 4095;
    int k  = g_idx[p];
    int pos = atomicAdd(&g_cur[b*KK + k], 1);
    g_sp[b*HWD + pos] = (uint16_t)hw;
    g_sk[b*HWD + pos] = (uint8_t)k;
}

// ---------------- K3d: zero cluster-sum buffer (replay-safe) ----------------
__global__ void kzero(){
    int i = blockIdx.x*256 + threadIdx.x;     // BB*KK*CC/4 float4s
    ((float4*)g_cl)[i] = make_float4(0.f,0.f,0.f,0.f);
}

// ---------------- K4: cluster sums via sorted runs (no per-element atomics) ------
// grid (64 cgroups, 8 batches). Each block: 16 channels. Channel row staged in
// shared; each thread owns 16 consecutive sorted positions and emits one global
// REDG per run of equal cluster id.
__global__ __launch_bounds__(256) void ksum(const float* __restrict__ x){
    int b = blockIdx.y, c0 = blockIdx.x*16;
    __shared__ float srow[HWD];               // 16 KB
    const int tid = threadIdx.x;
    const int i0  = tid*16;

    // per-thread sorted metadata (coalesced vector loads)
    union { uint4 v;    uint8_t  u[16]; } skv;
    union { uint4 v[2]; uint16_t u[16]; } spv;
    skv.v    = ((const uint4*)(g_sk + b*HWD))[tid];
    spv.v[0] = ((const uint4*)(g_sp + b*HWD))[2*tid];
    spv.v[1] = ((const uint4*)(g_sp + b*HWD))[2*tid + 1];

    for(int ci = 0; ci < 16; ci++){
        int c = c0 + ci;
        __syncthreads();
        const float4* row = (const float4*)(x + ((size_t)b*CC + c)*HWD);
        #pragma unroll
        for(int l = 0; l < 4; l++)
            ((float4*)srow)[tid + l*256] = row[tid + l*256];
        __syncthreads();

        int curk = skv.u[0];
        float s = 0.f;
        #pragma unroll
        for(int j = 0; j < 16; j++){
            int   k2 = skv.u[j];
            float v  = srow[spv.u[j]];
            if(k2 != curk){
                atomicAdd(&g_cl[((size_t)b*KK + curk)*CC + c], s);
                s = 0.f; curk = k2;
            }
            s += v;
        }
        atomicAdd(&g_cl[((size_t)b*KK + curk)*CC + c], s);
    }
}

// ---------------- K5: divide sums by max(count, 1) in place ----------------
__global__ void kdiv(){
    int bk = blockIdx.x;
    float cnt = fmaxf(g_cnt[bk], 1.0f);
    float inv = 1.0f / cnt;
    for(int c = threadIdx.x; c < CC; c += 256)
        g_cl[(size_t)bk*CC + c] *= inv;
}

// ---------------- K6: calibration weight w = exp(-mean_c (cl-x)^2) ----------------
__global__ __launch_bounds__(256) void kw(const float* __restrict__ x){
    int b = blockIdx.y;
    int p = blockIdx.x*256 + threadIdx.x;     // pixel within batch
    int k = g_idx[b*HWD + p];
    __shared__ float scl[KK][65];             // 16.6 KB chunk of local centroids
    const float* xb = x + (size_t)b*CC*HWD + p;
    float ssd = 0.f;
    for(int c0 = 0; c0 < CC; c0 += 64){
        __syncthreads();
        for(int i = threadIdx.x; i < KK*64; i += 256){
            int kk = i >> 6, ci = i & 63;
            scl[kk][ci] = g_cl[((size_t)b*KK + kk)*CC + c0 + ci];
        }
        __syncthreads();
        #pragma unroll 8
        for(int ci = 0; ci < 64; ci++){
            float d = scl[k][ci] - xb[(size_t)(c0+ci)*HWD];
            ssd += d*d;
        }
    }
    g_w[b*HWD + p] = expf(-ssd * (1.0f/1024.0f));
}

// ---------------- K7: x_cal = x + w*(cl - x) ----------------
__global__ void kxcal(const float* __restrict__ x){
    int e  = blockIdx.x*256 + threadIdx.x;
    int b  = e >> 22;
    int c  = (e >> 12) & 1023;
    int hw = e & 4095;
    int pidx = (b << 12) + hw;
    float xv  = x[e];
    int   k   = g_idx[pidx];
    float wv  = g_w[pidx];
    float clv = g_cl[((size_t)b*KK + k)*CC + c];
    g_xcal[e] = xv + wv*(clv - xv);
}

// ---------------- K8: 1x1 conv GEMM + bias + relu (packed f32x2 FMA) ----------------
// 128x128 tile per CTA, 8x8 micro-tile. W staged PRE-DUPLICATED as packed f32x2
// so the hot loop has no dup2 MOVs: 6 LDS.128 + 32 FFMA2 per kk (~84% fma issue).
__global__ __launch_bounds__(256,2) void kgemm(const float* __restrict__ Wt,
                                               const float* __restrict__ bias,
                                               float* __restrict__ out){
    const int bxp = blockIdx.x;   // pixel tile (32 of 128)
    const int byo = blockIdx.y;   // out-channel tile (8 of 128)
    const int b   = blockIdx.z;
    __shared__ unsigned long long sWd[16][128]; // [kk][o] duplicated pairs, 16 KB
    __shared__ float sX[16][128];               // [kk][p], 8 KB
    const int tid = threadIdx.x;
    const int tx = tid & 15, ty = tid >> 4;

    const float* Xb = g_xcal + (size_t)b*CC*HWD + bxp*128;
    const float* Wb = Wt + (size_t)byo*128*CC;

    unsigned long long acc[8][4];
    #pragma unroll
    for(int i = 0; i < 8; i++)
        #pragma unroll
        for(int j = 0; j < 4; j++) acc[i][j] = 0ull;

    float4 wreg[2], xreg[2];
    #pragma unroll
    for(int l = 0; l < 2; l++){
        int j = tid + l*256;
        int row = j >> 2, cc = (j & 3)*4;
        wreg[l] = *(const float4*)&Wb[(size_t)row*CC + cc];
        int kk = j >> 5, pq = (j & 31)*4;
        xreg[l] = *(const float4*)&Xb[(size_t)kk*HWD + pq];
    }

    for(int c0 = 0; c0 < CC; c0 += 16){
        __syncthreads();
        #pragma unroll
        for(int l = 0; l < 2; l++){
            int j = tid + l*256;
            int row = j >> 2, cc = (j & 3)*4;
            sWd[cc+0][row] = dup2(wreg[l].x);
            sWd[cc+1][row] = dup2(wreg[l].y);
            sWd[cc+2][row] = dup2(wreg[l].z);
            sWd[cc+3][row] = dup2(wreg[l].w);
            int kk = j >> 5, pq = (j & 31)*4;
            *(float4*)&sX[kk][pq] = xreg[l];
        }
        __syncthreads();
        if(c0 + 16 < CC){
            #pragma unroll
            for(int l = 0; l < 2; l++){
                int j = tid + l*256;
                int row = j >> 2, cc = (j & 3)*4;
                wreg[l] = *(const float4*)&Wb[(size_t)row*CC + c0 + 16 + cc];
                int kk = j >> 5, pq = (j & 31)*4;
                xreg[l] = *(const float4*)&Xb[(size_t)(c0 + 16 + kk)*HWD + pq];
            }
        }
        #pragma unroll
        for(int kk = 0; kk < 16; kk++){
            ulonglong2 a01 = *(const ulonglong2*)&sWd[kk][ty*8];
            ulonglong2 a23 = *(const ulonglong2*)&sWd[kk][ty*8 + 2];
            ulonglong2 a45 = *(const ulonglong2*)&sWd[kk][ty*8 + 4];
            ulonglong2 a67 = *(const ulonglong2*)&sWd[kk][ty*8 + 6];
            ulonglong2 b01 = *(const ulonglong2*)&sX[kk][tx*8];
            ulonglong2 b23 = *(const ulonglong2*)&sX[kk][tx*8 + 4];
            unsigned long long aa[8] = {a01.x,a01.y,a23.x,a23.y,a45.x,a45.y,a67.x,a67.y};
            #pragma unroll
            for(int oi = 0; oi < 8; oi++){
                ffma2(acc[oi][0], aa[oi], b01.x);
                ffma2(acc[oi][1], aa[oi], b01.y);
                ffma2(acc[oi][2], aa[oi], b23.x);
                ffma2(acc[oi][3], aa[oi], b23.y);
            }
        }
    }

    // epilogue: + bias, relu, store
    #pragma unroll
    for(int oi = 0; oi < 8; oi++){
        int o = byo*128 + ty*8 + oi;
        float bv = bias[o];
        float res[8];
        #pragma unroll
        for(int j = 0; j < 4; j++){
            float2 v = unpack2(acc[oi][j]);
            res[2*j]   = fmaxf(v.x + bv, 0.f);
            res[2*j+1] = fmaxf(v.y + bv, 0.f);
        }
        float* op = out + (size_t)b*CC*HWD + (size_t)o*HWD + bxp*128 + tx*8;
        *(float4*)op     = make_float4(res[0],res[1],res[2],res[3]);
        *(float4*)(op+4) = make_float4(res[4],res[5],res[6],res[7]);
    }
}

// ---------------- launch ----------------
extern "C" void kernel_launch(void* const* d_in, const int* in_sizes, int n_in,
                              void* d_out, int out_size){
    const float* x   = (const float*)d_in[0];
    const float* cen = (const float*)d_in[1];
    const float* fw  = (const float*)d_in[2];
    const float* fb  = (const float*)d_in[3];
    float* out = (float*)d_out;

    knorm   <<<KK, 256>>>(cen);
    kassign <<<PP/256, 256>>>(x);
    khist   <<<BB, 256>>>();
    kscan   <<<BB, KK>>>();
    kscatter<<<PP/256, 256>>>();
    kzero   <<<(BB*KK*CC/4)/256, 256>>>();
    ksum    <<<dim3(64, BB), 256>>>(x);
    kdiv    <<<BB*KK, 256>>>();
    kw      <<<dim3(HWD/256, BB), 256>>>(x);
    kxcal   <<<(int)(((size_t)BB*CC*HWD)/256), 256>>>(x);
    kgemm   <<<dim3(32, 8, BB), 256>>>(fw, fb, out);
}

// round 11
// speedup vs baseline: 2.4956x; 2.3389x over previous
#include <cuda_runtime.h>
#include <cuda_bf16.h>
#include <cstdint>

#define BB 8
#define CC 1024
#define HWD 4096
#define KK 64
#define PP (BB*HWD)   // 32768 pixels

// ---------------- scratch (device globals; no allocation allowed) ----------------
__device__ float    g_gnT[CC*KK];
__device__ int      g_idx[PP];
__device__ float    g_cnt[BB*KK];
__device__ int      g_icnt[BB*KK];
__device__ int      g_off[BB*KK];
__device__ int      g_cur[BB*KK];
__device__ uint16_t g_sp[PP];
__device__ uint8_t  g_sk[PP];
__device__ float    g_cl[BB*KK*CC];
__device__ float    g_w[PP];
__device__ __nv_bfloat16 g_xh[(size_t)PP*CC];   // x_cal hi, pixel-major [b*HWD+p][c]
__device__ __nv_bfloat16 g_xl[(size_t)PP*CC];   // x_cal lo
__device__ __nv_bfloat16 g_wh[CC*CC];           // W hi  [o][c]
__device__ __nv_bfloat16 g_wl[CC*CC];           // W lo

// ---------------- packed f32x2 helpers (kassign) ----------------
__device__ __forceinline__ void ffma2(unsigned long long &acc, unsigned long long a, unsigned long long b){
    asm("fma.rn.f32x2 %0, %1, %2, %0;" : "+l"(acc) : "l"(a), "l"(b));
}
__device__ __forceinline__ unsigned long long dup2(float v){
    unsigned long long r; unsigned int u = __float_as_uint(v);
    asm("mov.b64 %0, {%1, %1};" : "=l"(r) : "r"(u));
    return r;
}
__device__ __forceinline__ float2 unpack2(unsigned long long v){
    unsigned int lo, hi;
    asm("mov.b64 {%0, %1}, %2;" : "=r"(lo), "=r"(hi) : "l"(v));
    return make_float2(__uint_as_float(lo), __uint_as_float(hi));
}

// ---------------- smem / cp.async / mma helpers (baseline PTX, no 'a' features) ----
__device__ __forceinline__ uint32_t smem_u32(const void* p){
    uint32_t a;
    asm("{ .reg .u64 t; cvta.to.shared.u64 t, %1; cvt.u32.u64 %0, t; }" : "=r"(a) : "l"(p));
    return a;
}
#define CP_ASYNC16(sa, ga) asm volatile("cp.async.cg.shared.global [%0], [%1], 16;" :: "r"(sa), "l"(ga))
#define CP_COMMIT()        asm volatile("cp.async.commit_group;" ::: "memory")
#define CP_WAIT1()         asm volatile("cp.async.wait_group 1;" ::: "memory")

__device__ __forceinline__ void ldsm_x4(uint32_t* r, uint32_t addr){
    asm volatile("ldmatrix.sync.aligned.m8n8.x4.shared.b16 {%0,%1,%2,%3}, [%4];"
        : "=r"(r[0]), "=r"(r[1]), "=r"(r[2]), "=r"(r[3]) : "r"(addr));
}
__device__ __forceinline__ void mma_bf16(float* d, const uint32_t* a, const uint32_t* b){
    asm volatile("mma.sync.aligned.m16n8k16.row.col.f32.bf16.bf16.f32 "
        "{%0,%1,%2,%3}, {%4,%5,%6,%7}, {%8,%9}, {%0,%1,%2,%3};"
        : "+f"(d[0]), "+f"(d[1]), "+f"(d[2]), "+f"(d[3])
        : "r"(a[0]), "r"(a[1]), "r"(a[2]), "r"(a[3]), "r"(b[0]), "r"(b[1]));
}
#define SW128(o) ((o) ^ (((o) >> 3) & 0x70))

// ---------------- K1: normalize centroids, transposed [c][k] ----------------
__global__ void knorm(const float* __restrict__ cen){
    int k = blockIdx.x;
    __shared__ float red[256];
    float s = 0.f;
    for(int c = threadIdx.x; c < CC; c += 256){ float v = cen[k*CC+c]; s += v*v; }
    red[threadIdx.x] = s; __syncthreads();
    for(int o = 128; o > 0; o >>= 1){
        if(threadIdx.x < o) red[threadIdx.x] += red[threadIdx.x + o];
        __syncthreads();
    }
    float inv = 1.0f / fmaxf(sqrtf(red[0]), 1e-12f);
    for(int c = threadIdx.x; c < CC; c += 256) g_gnT[c*KK + k] = cen[k*CC+c] * inv;
}

// ---------------- K2: nearest-centroid assignment ----------------
__global__ __launch_bounds__(256) void kassign(const float* __restrict__ x){
    int p  = blockIdx.x*256 + threadIdx.x;
    int b  = p >> 12, hw = p & 4095;
    const float* xb = x + (size_t)b*CC*HWD + hw;
    __shared__ ulonglong2 sg[1024];
    unsigned long long sims[32];
    #pragma unroll
    for(int i = 0; i < 32; i++) sims[i] = 0ull;
    for(int c0 = 0; c0 < CC; c0 += 64){
        __syncthreads();
        const float4* src = (const float4*)(g_gnT + c0*KK);
        #pragma unroll
        for(int l = 0; l < 4; l++)
            ((float4*)sg)[threadIdx.x + l*256] = src[threadIdx.x + l*256];
        __syncthreads();
        #pragma unroll 8
        for(int ci = 0; ci < 64; ci++){
            float xv = xb[(size_t)(c0+ci)*HWD];
            unsigned long long xd = dup2(xv);
            const ulonglong2* row = &sg[ci*16];
            #pragma unroll
            for(int j = 0; j < 16; j++){
                ulonglong2 g = row[j];
                ffma2(sims[2*j],   xd, g.x);
                ffma2(sims[2*j+1], xd, g.y);
            }
        }
    }
    float best = -1e30f; int bi = 0;
    #pragma unroll
    for(int i = 0; i < 32; i++){
        float2 v = unpack2(sims[i]);
        if(v.x > best){ best = v.x; bi = 2*i;   }
        if(v.y > best){ best = v.y; bi = 2*i+1; }
    }
    g_idx[p] = bi;
}

// ---------------- K3: histogram / scan / scatter / zero ----------------
__global__ void khist(){
    __shared__ int cnt[KK];
    if(threadIdx.x < KK) cnt[threadIdx.x] = 0;
    __syncthreads();
    int b = blockIdx.x;
    for(int p = threadIdx.x; p < HWD; p += 256) atomicAdd(&cnt[g_idx[b*HWD + p]], 1);
    __syncthreads();
    if(threadIdx.x < KK){
        g_cnt [b*KK + threadIdx.x] = (float)cnt[threadIdx.x];
        g_icnt[b*KK + threadIdx.x] = cnt[threadIdx.x];
    }
}
__global__ void kscan(){
    int b = blockIdx.x, t = threadIdx.x;
    __shared__ int s[KK];
    s[t] = g_icnt[b*KK + t];
    __syncthreads();
    if(t == 0){ int acc = 0; for(int k = 0; k < KK; k++){ int c = s[k]; s[k] = acc; acc += c; } }
    __syncthreads();
    g_off[b*KK + t] = s[t];
    g_cur[b*KK + t] = s[t];
}
__global__ void kscatter(){
    int p  = blockIdx.x*256 + threadIdx.x;
    int b  = p >> 12, hw = p & 4095;
    int k  = g_idx[p];
    int pos = atomicAdd(&g_cur[b*KK + k], 1);
    g_sp[b*HWD + pos] = (uint16_t)hw;
    g_sk[b*HWD + pos] = (uint8_t)k;
}
__global__ void kzero(){
    int i = blockIdx.x*256 + threadIdx.x;
    ((float4*)g_cl)[i] = make_float4(0.f,0.f,0.f,0.f);
}

// ---------------- K4: cluster sums via sorted runs ----------------
__global__ __launch_bounds__(256) void ksum(const float* __restrict__ x){
    int b = blockIdx.y, c0 = blockIdx.x*16;
    __shared__ float srow[HWD];
    const int tid = threadIdx.x;
    union { uint4 v;    uint8_t  u[16]; } skv;
    union { uint4 v[2]; uint16_t u[16]; } spv;
    skv.v    = ((const uint4*)(g_sk + b*HWD))[tid];
    spv.v[0] = ((const uint4*)(g_sp + b*HWD))[2*tid];
    spv.v[1] = ((const uint4*)(g_sp + b*HWD))[2*tid + 1];
    for(int ci = 0; ci < 16; ci++){
        int c = c0 + ci;
        __syncthreads();
        const float4* row = (const float4*)(x + ((size_t)b*CC + c)*HWD);
        #pragma unroll
        for(int l = 0; l < 4; l++)
            ((float4*)srow)[tid + l*256] = row[tid + l*256];
        __syncthreads();
        int curk = skv.u[0];
        float s = 0.f;
        #pragma unroll
        for(int j = 0; j < 16; j++){
            int   k2 = skv.u[j];
            float v  = srow[spv.u[j]];
            if(k2 != curk){
                atomicAdd(&g_cl[((size_t)b*KK + curk)*CC + c], s);
                s = 0.f; curk = k2;
            }
            s += v;
        }
        atomicAdd(&g_cl[((size_t)b*KK + curk)*CC + c], s);
    }
}

// ---------------- K5: divide ----------------
__global__ void kdiv(){
    int bk = blockIdx.x;
    float inv = 1.0f / fmaxf(g_cnt[bk], 1.0f);
    for(int c = threadIdx.x; c < CC; c += 256)
        g_cl[(size_t)bk*CC + c] *= inv;
}

// ---------------- K6: calibration weight ----------------
__global__ __launch_bounds__(256) void kw(const float* __restrict__ x){
    int b = blockIdx.y;
    int p = blockIdx.x*256 + threadIdx.x;
    int k = g_idx[b*HWD + p];
    __shared__ float scl[KK][65];
    const float* xb = x + (size_t)b*CC*HWD + p;
    float ssd = 0.f;
    for(int c0 = 0; c0 < CC; c0 += 64){
        __syncthreads();
        for(int i = threadIdx.x; i < KK*64; i += 256){
            int kk = i >> 6, ci = i & 63;
            scl[kk][ci] = g_cl[((size_t)b*KK + kk)*CC + c0 + ci];
        }
        __syncthreads();
        #pragma unroll 8
        for(int ci = 0; ci < 64; ci++){
            float d = scl[k][ci] - xb[(size_t)(c0+ci)*HWD];
            ssd += d*d;
        }
    }
    g_w[b*HWD + p] = expf(-ssd * (1.0f/1024.0f));
}

// ---------------- K6b: split W into bf16 hi/lo ----------------
__global__ void kwsplit(const float* __restrict__ Wt){
    int o = blockIdx.x;
    for(int c = threadIdx.x; c < CC; c += 256){
        float v = Wt[o*CC + c];
        __nv_bfloat16 h = __float2bfloat16_rn(v);
        g_wh[o*CC + c] = h;
        g_wl[o*CC + c] = __float2bfloat16_rn(v - __bfloat162float(h));
    }
}

// ---------------- K7: x_cal, transpose to [p][c], split bf16 hi/lo ----------------
__global__ __launch_bounds__(256) void kconv(const float* __restrict__ x){
    int b  = blockIdx.z;
    int p0 = blockIdx.x*64;
    int c0 = blockIdx.y*64;
    __shared__ float tile[64][65];
    __shared__ float s_w[64];
    __shared__ int   s_k[64];
    int tid = threadIdx.x;
    if(tid < 64){
        s_w[tid] = g_w [b*HWD + p0 + tid];
        s_k[tid] = g_idx[b*HWD + p0 + tid];
    }
    __syncthreads();
    int pi = tid & 63, cq = tid >> 6;
    #pragma unroll
    for(int l = 0; l < 16; l++){
        int ci = l*4 + cq, c = c0 + ci;
        float xv = x[((size_t)b*CC + c)*HWD + p0 + pi];
        int   k  = s_k[pi];
        float cl = g_cl[((size_t)b*KK + k)*CC + c];
        tile[pi][ci] = xv + s_w[pi]*(cl - xv);
    }
    __syncthreads();
    int ci2 = tid & 63, pq = tid >> 6;
    #pragma unroll
    for(int l = 0; l < 16; l++){
        int pi2 = l*4 + pq;
        float v = tile[pi2][ci2];
        __nv_bfloat16 h = __float2bfloat16_rn(v);
        size_t idx = ((size_t)(b*HWD + p0 + pi2))*CC + c0 + ci2;
        g_xh[idx] = h;
        g_xl[idx] = __float2bfloat16_rn(v - __bfloat162float(h));
    }
}

// ---------------- K8: bf16 3-term split GEMM via ldmatrix + mma.sync ----------------
// D[p,o] = sum_c Xcal[p,c]*W[o,c].  CTA: 128 pixels x 128 o.  K staged 64/chunk,
// 2-stage cp.async pipeline.  Warp grid 4(M) x 2(N): each warp 32x64.
// Terms: Ah*Bh + Ah*Bl + Al*Bh (fp32 accum).
#define TILE_SZ  16384            // 128 rows x 64 bf16 (128B rows, SW128)
#define STAGE_SZ (4*TILE_SZ)      // Xh, Xl, Wh, Wl
#define GEMM_SMEM (2*STAGE_SZ)    // 131072

__global__ __launch_bounds__(256, 1) void kgemm_mma(const float* __restrict__ bias,
                                                    float* __restrict__ out){
    extern __shared__ char smem[];
    const uint32_t sbase = smem_u32(smem);
    const int tid  = threadIdx.x;
    const int wid  = tid >> 5, lane = tid & 31;
    const int wm   = wid & 3,  wn   = wid >> 2;     // 4 x 2 warp grid
    const int o_base = blockIdx.x*128;
    const int p0     = blockIdx.y*128;
    const int b      = blockIdx.z;

    const char* gx[4];
    gx[0] = (const char*)g_xh + ((size_t)(b*HWD + p0))*CC*2;
    gx[1] = (const char*)g_xl + ((size_t)(b*HWD + p0))*CC*2;
    gx[2] = (const char*)g_wh + (size_t)o_base*CC*2;
    gx[3] = (const char*)g_wl + (size_t)o_base*CC*2;

    // loader: per stage, 4 tiles x 4 cp.asyncs/thread (16B each)
    const int lr = tid >> 3;            // row 0..31 base (rows covered via +32*l? no: j= tid+l*256)
    auto load_stage = [&](int st, int chunk){
        uint32_t s0 = sbase + st*STAGE_SZ;
        size_t cb = (size_t)chunk*128;  // 64 bf16 = 128 B within a row
        #pragma unroll
        for(int t = 0; t < 4; t++){
            #pragma unroll
            for(int l = 0; l < 4; l++){
                int j = tid + l*256;
                int r = j >> 3, s = (j & 7)*16;
                uint32_t so = s0 + t*TILE_SZ + SW128((uint32_t)(r*128 + s));
                const char* ga = gx[t] + (size_t)r*(CC*2) + cb + s;
                CP_ASYNC16(so, ga);
            }
        }
    };
    (void)lr;

    float acc[2][8][4];
    #pragma unroll
    for(int m = 0; m < 2; m++)
        #pragma unroll
        for(int n = 0; n < 8; n++)
            #pragma unroll
            for(int q = 0; q < 4; q++) acc[m][n][q] = 0.f;

    // ldmatrix per-lane offsets (within a tile, before swizzle add)
    const int arow = wm*32 + (lane & 15);          // + mt*16
    const int acol = (lane >> 4)*16;               // byte offset of k-half
    const int brow = wn*64 + (lane & 7) + ((lane >> 4) & 1)*8;  // + nt2*16
    const int bcol = ((lane >> 3) & 1)*16;

    load_stage(0, 0);
    CP_COMMIT();

    for(int i = 0; i < 16; i++){
        const int st = i & 1;
        if(i + 1 < 16) load_stage(st ^ 1, i + 1);
        CP_COMMIT();
        CP_WAIT1();
        __syncthreads();

        const uint32_t xh0 = sbase + st*STAGE_SZ;
        const uint32_t xl0 = xh0 + TILE_SZ;
        const uint32_t wh0 = xh0 + 2*TILE_SZ;
        const uint32_t wl0 = xh0 + 3*TILE_SZ;

        #pragma unroll
        for(int ks = 0; ks < 4; ks++){
            const int kb = ks*32;   // byte offset of this k16 within 128B row
            uint32_t ah[2][4], al[2][4], bh[4][4], bl[4][4];
            #pragma unroll
            for(int mt = 0; mt < 2; mt++){
                uint32_t off = SW128((uint32_t)((arow + mt*16)*128 + kb + acol));
                ldsm_x4(ah[mt], xh0 + off);
                ldsm_x4(al[mt], xl0 + off);
            }
            #pragma unroll
            for(int nt = 0; nt < 4; nt++){
                uint32_t off = SW128((uint32_t)((brow + nt*16)*128 + kb + bcol));
                ldsm_x4(bh[nt], wh0 + off);
                ldsm_x4(bl[nt], wl0 + off);
            }
            #pragma unroll
            for(int mt = 0; mt < 2; mt++){
                #pragma unroll
                for(int nt = 0; nt < 4; nt++){
                    mma_bf16(acc[mt][2*nt],   ah[mt], &bh[nt][0]);
                    mma_bf16(acc[mt][2*nt+1], ah[mt], &bh[nt][2]);
                    mma_bf16(acc[mt][2*nt],   ah[mt], &bl[nt][0]);
                    mma_bf16(acc[mt][2*nt+1], ah[mt], &bl[nt][2]);
                    mma_bf16(acc[mt][2*nt],   al[mt], &bh[nt][0]);
                    mma_bf16(acc[mt][2*nt+1], al[mt], &bh[nt][2]);
                }
            }
        }
        __syncthreads();
    }

    // epilogue: bias + relu, out[b][o][p]
    const int g = lane >> 2, t4 = lane & 3;
    float* ob = out + (size_t)b*CC*HWD;
    #pragma unroll
    for(int n = 0; n < 8; n++){
        int o = o_base + wn*64 + n*8 + t4*2;
        float b0 = bias[o], b1 = bias[o+1];
        float* c0p = ob + (size_t)o*HWD;
        float* c1p = ob + (size_t)(o+1)*HWD;
        #pragma unroll
        for(int m = 0; m < 2; m++){
            int p = p0 + wm*32 + m*16 + g;
            c0p[p]     = fmaxf(acc[m][n][0] + b0, 0.f);
            c1p[p]     = fmaxf(acc[m][n][1] + b1, 0.f);
            c0p[p + 8] = fmaxf(acc[m][n][2] + b0, 0.f);
            c1p[p + 8] = fmaxf(acc[m][n][3] + b1, 0.f);
        }
    }
}

// ---------------- launch ----------------
extern "C" void kernel_launch(void* const* d_in, const int* in_sizes, int n_in,
                              void* d_out, int out_size){
    const float* x   = (const float*)d_in[0];
    const float* cen = (const float*)d_in[1];
    const float* fw  = (const float*)d_in[2];
    const float* fb  = (const float*)d_in[3];
    float* out = (float*)d_out;

    cudaFuncSetAttribute(kgemm_mma, cudaFuncAttributeMaxDynamicSharedMemorySize, GEMM_SMEM);

    knorm    <<<KK, 256>>>(cen);
    kassign  <<<PP/256, 256>>>(x);
    khist    <<<BB, 256>>>();
    kscan    <<<BB, KK>>>();
    kscatter <<<PP/256, 256>>>();
    kzero    <<<(BB*KK*CC/4)/256, 256>>>();
    ksum     <<<dim3(64, BB), 256>>>(x);
    kdiv     <<<BB*KK, 256>>>();
    kw       <<<dim3(HWD/256, BB), 256>>>(x);
    kwsplit  <<<CC, 256>>>(fw);
    kconv    <<<dim3(HWD/64, CC/64, BB), 256>>>(x);
    kgemm_mma<<<dim3(8, 32, BB), 256, GEMM_SMEM>>>(fb, out);
}

// round 12
// speedup vs baseline: 2.6322x; 1.0547x over previous
#include <cuda_runtime.h>
#include <cuda_bf16.h>
#include <cstdint>

#define BB 8
#define CC 1024
#define HWD 4096
#define KK 64
#define PP (BB*HWD)   // 32768 pixels

// ---------------- scratch (device globals; no allocation allowed) ----------------
__device__ float    g_gnT[CC*KK];
__device__ int      g_idx[PP];
__device__ float    g_cnt[BB*KK];
__device__ int      g_icnt[BB*KK];
__device__ int      g_off[BB*KK];
__device__ int      g_cur[BB*KK];
__device__ uint16_t g_sp[PP];
__device__ uint8_t  g_sk[PP];
__device__ float    g_cl[BB*KK*CC];
__device__ float    g_w[PP];
__device__ __nv_bfloat16 g_xh[(size_t)PP*CC];   // x_cal hi, pixel-major [b*HWD+p][c]
__device__ __nv_bfloat16 g_xl[(size_t)PP*CC];   // x_cal lo
__device__ __nv_bfloat16 g_wh[CC*CC];           // W hi  [o][c]
__device__ __nv_bfloat16 g_wl[CC*CC];           // W lo

// ---------------- packed f32x2 helpers (kassign) ----------------
__device__ __forceinline__ void ffma2(unsigned long long &acc, unsigned long long a, unsigned long long b){
    asm("fma.rn.f32x2 %0, %1, %2, %0;" : "+l"(acc) : "l"(a), "l"(b));
}
__device__ __forceinline__ unsigned long long dup2(float v){
    unsigned long long r; unsigned int u = __float_as_uint(v);
    asm("mov.b64 %0, {%1, %1};" : "=l"(r) : "r"(u));
    return r;
}
__device__ __forceinline__ float2 unpack2(unsigned long long v){
    unsigned int lo, hi;
    asm("mov.b64 {%0, %1}, %2;" : "=r"(lo), "=r"(hi) : "l"(v));
    return make_float2(__uint_as_float(lo), __uint_as_float(hi));
}

// ---------------- smem / cp.async / mma helpers (baseline PTX, no 'a' features) ----
__device__ __forceinline__ uint32_t smem_u32(const void* p){
    uint32_t a;
    asm("{ .reg .u64 t; cvta.to.shared.u64 t, %1; cvt.u32.u64 %0, t; }" : "=r"(a) : "l"(p));
    return a;
}
#define CP_ASYNC16(sa, ga) asm volatile("cp.async.cg.shared.global [%0], [%1], 16;" :: "r"(sa), "l"(ga))
#define CP_COMMIT()        asm volatile("cp.async.commit_group;" ::: "memory")
#define CP_WAIT0()         asm volatile("cp.async.wait_group 0;" ::: "memory")

__device__ __forceinline__ void ldsm_x4(uint32_t* r, uint32_t addr){
    asm volatile("ldmatrix.sync.aligned.m8n8.x4.shared.b16 {%0,%1,%2,%3}, [%4];"
        : "=r"(r[0]), "=r"(r[1]), "=r"(r[2]), "=r"(r[3]) : "r"(addr));
}
__device__ __forceinline__ void mma_bf16(float* d, const uint32_t* a, const uint32_t* b){
    asm volatile("mma.sync.aligned.m16n8k16.row.col.f32.bf16.bf16.f32 "
        "{%0,%1,%2,%3}, {%4,%5,%6,%7}, {%8,%9}, {%0,%1,%2,%3};"
        : "+f"(d[0]), "+f"(d[1]), "+f"(d[2]), "+f"(d[3])
        : "r"(a[0]), "r"(a[1]), "r"(a[2]), "r"(a[3]), "r"(b[0]), "r"(b[1]));
}
#define SW128(o) ((o) ^ (((o) >> 3) & 0x70))

// ---------------- K1: normalize centroids, transposed [c][k] ----------------
__global__ void knorm(const float* __restrict__ cen){
    int k = blockIdx.x;
    __shared__ float red[256];
    float s = 0.f;
    for(int c = threadIdx.x; c < CC; c += 256){ float v = cen[k*CC+c]; s += v*v; }
    red[threadIdx.x] = s; __syncthreads();
    for(int o = 128; o > 0; o >>= 1){
        if(threadIdx.x < o) red[threadIdx.x] += red[threadIdx.x + o];
        __syncthreads();
    }
    float inv = 1.0f / fmaxf(sqrtf(red[0]), 1e-12f);
    for(int c = threadIdx.x; c < CC; c += 256) g_gnT[c*KK + k] = cen[k*CC+c] * inv;
}

// ---------------- K2: nearest-centroid assignment ----------------
__global__ __launch_bounds__(256) void kassign(const float* __restrict__ x){
    int p  = blockIdx.x*256 + threadIdx.x;
    int b  = p >> 12, hw = p & 4095;
    const float* xb = x + (size_t)b*CC*HWD + hw;
    __shared__ ulonglong2 sg[1024];
    unsigned long long sims[32];
    #pragma unroll
    for(int i = 0; i < 32; i++) sims[i] = 0ull;
    for(int c0 = 0; c0 < CC; c0 += 64){
        __syncthreads();
        const float4* src = (const float4*)(g_gnT + c0*KK);
        #pragma unroll
        for(int l = 0; l < 4; l++)
            ((float4*)sg)[threadIdx.x + l*256] = src[threadIdx.x + l*256];
        __syncthreads();
        #pragma unroll 8
        for(int ci = 0; ci < 64; ci++){
            float xv = xb[(size_t)(c0+ci)*HWD];
            unsigned long long xd = dup2(xv);
            const ulonglong2* row = &sg[ci*16];
            #pragma unroll
            for(int j = 0; j < 16; j++){
                ulonglong2 g = row[j];
                ffma2(sims[2*j],   xd, g.x);
                ffma2(sims[2*j+1], xd, g.y);
            }
        }
    }
    float best = -1e30f; int bi = 0;
    #pragma unroll
    for(int i = 0; i < 32; i++){
        float2 v = unpack2(sims[i]);
        if(v.x > best){ best = v.x; bi = 2*i;   }
        if(v.y > best){ best = v.y; bi = 2*i+1; }
    }
    g_idx[p] = bi;
}

// ---------------- K3: histogram / scan / scatter / zero ----------------
__global__ void khist(){
    __shared__ int cnt[KK];
    if(threadIdx.x < KK) cnt[threadIdx.x] = 0;
    __syncthreads();
    int b = blockIdx.x;
    for(int p = threadIdx.x; p < HWD; p += 256) atomicAdd(&cnt[g_idx[b*HWD + p]], 1);
    __syncthreads();
    if(threadIdx.x < KK){
        g_cnt [b*KK + threadIdx.x] = (float)cnt[threadIdx.x];
        g_icnt[b*KK + threadIdx.x] = cnt[threadIdx.x];
    }
}
__global__ void kscan(){
    int b = blockIdx.x, t = threadIdx.x;
    __shared__ int s[KK];
    s[t] = g_icnt[b*KK + t];
    __syncthreads();
    if(t == 0){ int acc = 0; for(int k = 0; k < KK; k++){ int c = s[k]; s[k] = acc; acc += c; } }
    __syncthreads();
    g_off[b*KK + t] = s[t];
    g_cur[b*KK + t] = s[t];
}
__global__ void kscatter(){
    int p  = blockIdx.x*256 + threadIdx.x;
    int b  = p >> 12, hw = p & 4095;
    int k  = g_idx[p];
    int pos = atomicAdd(&g_cur[b*KK + k], 1);
    g_sp[b*HWD + pos] = (uint16_t)hw;
    g_sk[b*HWD + pos] = (uint8_t)k;
}
__global__ void kzero(){
    int i = blockIdx.x*256 + threadIdx.x;
    ((float4*)g_cl)[i] = make_float4(0.f,0.f,0.f,0.f);
}

// ---------------- K4: cluster sums via sorted runs ----------------
__global__ __launch_bounds__(256) void ksum(const float* __restrict__ x){
    int b = blockIdx.y, c0 = blockIdx.x*16;
    __shared__ float srow[HWD];
    const int tid = threadIdx.x;
    union { uint4 v;    uint8_t  u[16]; } skv;
    union { uint4 v[2]; uint16_t u[16]; } spv;
    skv.v    = ((const uint4*)(g_sk + b*HWD))[tid];
    spv.v[0] = ((const uint4*)(g_sp + b*HWD))[2*tid];
    spv.v[1] = ((const uint4*)(g_sp + b*HWD))[2*tid + 1];
    for(int ci = 0; ci < 16; ci++){
        int c = c0 + ci;
        __syncthreads();
        const float4* row = (const float4*)(x + ((size_t)b*CC + c)*HWD);
        #pragma unroll
        for(int l = 0; l < 4; l++)
            ((float4*)srow)[tid + l*256] = row[tid + l*256];
        __syncthreads();
        int curk = skv.u[0];
        float s = 0.f;
        #pragma unroll
        for(int j = 0; j < 16; j++){
            int   k2 = skv.u[j];
            float v  = srow[spv.u[j]];
            if(k2 != curk){
                atomicAdd(&g_cl[((size_t)b*KK + curk)*CC + c], s);
                s = 0.f; curk = k2;
            }
            s += v;
        }
        atomicAdd(&g_cl[((size_t)b*KK + curk)*CC + c], s);
    }
}

// ---------------- K5: divide ----------------
__global__ void kdiv(){
    int bk = blockIdx.x;
    float inv = 1.0f / fmaxf(g_cnt[bk], 1.0f);
    for(int c = threadIdx.x; c < CC; c += 256)
        g_cl[(size_t)bk*CC + c] *= inv;
}

// ---------------- K6: calibration weight ----------------
__global__ __launch_bounds__(256) void kw(const float* __restrict__ x){
    int b = blockIdx.y;
    int p = blockIdx.x*256 + threadIdx.x;
    int k = g_idx[b*HWD + p];
    __shared__ float scl[KK][65];
    const float* xb = x + (size_t)b*CC*HWD + p;
    float ssd = 0.f;
    for(int c0 = 0; c0 < CC; c0 += 64){
        __syncthreads();
        for(int i = threadIdx.x; i < KK*64; i += 256){
            int kk = i >> 6, ci = i & 63;
            scl[kk][ci] = g_cl[((size_t)b*KK + kk)*CC + c0 + ci];
        }
        __syncthreads();
        #pragma unroll 8
        for(int ci = 0; ci < 64; ci++){
            float d = scl[k][ci] - xb[(size_t)(c0+ci)*HWD];
            ssd += d*d;
        }
    }
    g_w[b*HWD + p] = expf(-ssd * (1.0f/1024.0f));
}

// ---------------- K6b: split W into bf16 hi/lo ----------------
__global__ void kwsplit(const float* __restrict__ Wt){
    int o = blockIdx.x;
    for(int c = threadIdx.x; c < CC; c += 256){
        float v = Wt[o*CC + c];
        __nv_bfloat16 h = __float2bfloat16_rn(v);
        g_wh[o*CC + c] = h;
        g_wl[o*CC + c] = __float2bfloat16_rn(v - __bfloat162float(h));
    }
}

// ---------------- K7: x_cal, transpose to [p][c], split bf16 hi/lo ----------------
__global__ __launch_bounds__(256) void kconv(const float* __restrict__ x){
    int b  = blockIdx.z;
    int p0 = blockIdx.x*64;
    int c0 = blockIdx.y*64;
    __shared__ float tile[64][65];
    __shared__ float s_w[64];
    __shared__ int   s_k[64];
    int tid = threadIdx.x;
    if(tid < 64){
        s_w[tid] = g_w [b*HWD + p0 + tid];
        s_k[tid] = g_idx[b*HWD + p0 + tid];
    }
    __syncthreads();
    int pi = tid & 63, cq = tid >> 6;
    #pragma unroll
    for(int l = 0; l < 16; l++){
        int ci = l*4 + cq, c = c0 + ci;
        float xv = x[((size_t)b*CC + c)*HWD + p0 + pi];
        int   k  = s_k[pi];
        float cl = g_cl[((size_t)b*KK + k)*CC + c];
        tile[pi][ci] = xv + s_w[pi]*(cl - xv);
    }
    __syncthreads();
    int ci2 = tid & 63, pq = tid >> 6;
    #pragma unroll
    for(int l = 0; l < 16; l++){
        int pi2 = l*4 + pq;
        float v = tile[pi2][ci2];
        __nv_bfloat16 h = __float2bfloat16_rn(v);
        size_t idx = ((size_t)(b*HWD + p0 + pi2))*CC + c0 + ci2;
        g_xh[idx] = h;
        g_xl[idx] = __float2bfloat16_rn(v - __bfloat162float(h));
    }
}

// ---------------- K8: bf16 3-term split GEMM via ldmatrix + mma.sync ----------------
// CTA tile: 128 pixels x 64 out-ch.  Stage 48KB (Xh16K|Xl16K|Wh8K|Wl8K), 2 stages
// = 96KB -> 2 CTAs/SM.  Single __syncthreads per K-chunk; cp.async for chunk i+1
// overlaps compute of chunk i.  Warp grid 4(M)x2(N): each warp 32x32.
#define XT_SZ    16384
#define WT_SZ    8192
#define STAGE_SZ (2*XT_SZ + 2*WT_SZ)      // 49152
#define GEMM_SMEM (2*STAGE_SZ)            // 98304

__global__ __launch_bounds__(256, 2) void kgemm_mma(const float* __restrict__ bias,
                                                    float* __restrict__ out){
    extern __shared__ char smem[];
    const uint32_t sbase = smem_u32(smem);
    const int tid  = threadIdx.x;
    const int wid  = tid >> 5, lane = tid & 31;
    const int wm   = wid & 3,  wn   = wid >> 2;     // 4 x 2 warp grid
    const int o_base = blockIdx.x*64;
    const int p0     = blockIdx.y*128;
    const int b      = blockIdx.z;

    const char* xh_b = (const char*)g_xh + ((size_t)(b*HWD + p0))*CC*2;
    const char* xl_b = (const char*)g_xl + ((size_t)(b*HWD + p0))*CC*2;
    const char* wh_b = (const char*)g_wh + (size_t)o_base*CC*2;
    const char* wl_b = (const char*)g_wl + (size_t)o_base*CC*2;

    auto load_stage = [&](int st, int chunk){
        uint32_t s0 = sbase + st*STAGE_SZ;
        size_t cb = (size_t)chunk*128;            // 64 bf16 = 128 B within a row
        #pragma unroll
        for(int l = 0; l < 4; l++){               // X tiles: 128 rows
            int j = tid + l*256;
            int r = j >> 3, s = (j & 7)*16;
            uint32_t so = SW128((uint32_t)(r*128 + s));
            size_t go = (size_t)r*(CC*2) + cb + s;
            CP_ASYNC16(s0 + so,         xh_b + go);
            CP_ASYNC16(s0 + XT_SZ + so, xl_b + go);
        }
        #pragma unroll
        for(int l = 0; l < 2; l++){               // W tiles: 64 rows
            int j = tid + l*256;
            int r = j >> 3, s = (j & 7)*16;
            uint32_t so = SW128((uint32_t)(r*128 + s));
            size_t go = (size_t)r*(CC*2) + cb + s;
            CP_ASYNC16(s0 + 2*XT_SZ + so,         wh_b + go);
            CP_ASYNC16(s0 + 2*XT_SZ + WT_SZ + so, wl_b + go);
        }
    };

    float acc[2][4][4];
    #pragma unroll
    for(int m = 0; m < 2; m++)
        #pragma unroll
        for(int n = 0; n < 4; n++)
            #pragma unroll
            for(int q = 0; q < 4; q++) acc[m][n][q] = 0.f;

    // ldmatrix per-lane offsets (within a tile, before swizzle)
    const int arow = wm*32 + (lane & 15);                       // + mt*16
    const int acol = (lane >> 4)*16;                            // k-half byte offset
    const int brow = wn*32 + (lane & 7) + ((lane >> 4) & 1)*8;  // + nt*16
    const int bcol = ((lane >> 3) & 1)*16;

    load_stage(0, 0);
    CP_COMMIT();

    for(int i = 0; i < 16; i++){
        const int st = i & 1;
        CP_WAIT0();              // chunk i resident (only group i pending here)
        __syncthreads();         // all warps done computing chunk i-1 (buffer st^1)
        if(i + 1 < 16){
            load_stage(st ^ 1, i + 1);
            CP_COMMIT();
        }

        const uint32_t xh0 = sbase + st*STAGE_SZ;
        const uint32_t xl0 = xh0 + XT_SZ;
        const uint32_t wh0 = xh0 + 2*XT_SZ;
        const uint32_t wl0 = wh0 + WT_SZ;

        #pragma unroll
        for(int ks = 0; ks < 4; ks++){
            const int kb = ks*32;    // k16 byte offset within 128B row
            uint32_t ah[2][4], al[2][4], bh[2][4], bl[2][4];
            #pragma unroll
            for(int mt = 0; mt < 2; mt++){
                uint32_t off = SW128((uint32_t)((arow + mt*16)*128 + kb + acol));
                ldsm_x4(ah[mt], xh0 + off);
                ldsm_x4(al[mt], xl0 + off);
            }
            #pragma unroll
            for(int nt = 0; nt < 2; nt++){
                uint32_t off = SW128((uint32_t)((brow + nt*16)*128 + kb + bcol));
                ldsm_x4(bh[nt], wh0 + off);
                ldsm_x4(bl[nt], wl0 + off);
            }
            #pragma unroll
            for(int mt = 0; mt < 2; mt++){
                #pragma unroll
                for(int nt = 0; nt < 2; nt++){
                    mma_bf16(acc[mt][2*nt],   ah[mt], &bh[nt][0]);
                    mma_bf16(acc[mt][2*nt+1], ah[mt], &bh[nt][2]);
                    mma_bf16(acc[mt][2*nt],   ah[mt], &bl[nt][0]);
                    mma_bf16(acc[mt][2*nt+1], ah[mt], &bl[nt][2]);
                    mma_bf16(acc[mt][2*nt],   al[mt], &bh[nt][0]);
                    mma_bf16(acc[mt][2*nt+1], al[mt], &bh[nt][2]);
                }
            }
        }
    }

    // epilogue: bias + relu, out[b][o][p]
    const int g = lane >> 2, t4 = lane & 3;
    float* ob = out + (size_t)b*CC*HWD;
    #pragma unroll
    for(int n = 0; n < 4; n++){
        int o = o_base + wn*32 + n*8 + t4*2;
        float b0 = bias[o], b1 = bias[o+1];
        float* c0p = ob + (size_t)o*HWD;
        float* c1p = ob + (size_t)(o+1)*HWD;
        #pragma unroll
        for(int m = 0; m < 2; m++){
            int p = p0 + wm*32 + m*16 + g;
            c0p[p]     = fmaxf(acc[m][n][0] + b0, 0.f);
            c1p[p]     = fmaxf(acc[m][n][1] + b1, 0.f);
            c0p[p + 8] = fmaxf(acc[m][n][2] + b0, 0.f);
            c1p[p + 8] = fmaxf(acc[m][n][3] + b1, 0.f);
        }
    }
}

// ---------------- launch ----------------
extern "C" void kernel_launch(void* const* d_in, const int* in_sizes, int n_in,
                              void* d_out, int out_size){
    const float* x   = (const float*)d_in[0];
    const float* cen = (const float*)d_in[1];
    const float* fw  = (const float*)d_in[2];
    const float* fb  = (const float*)d_in[3];
    float* out = (float*)d_out;

    cudaFuncSetAttribute(kgemm_mma, cudaFuncAttributeMaxDynamicSharedMemorySize, GEMM_SMEM);

    // independent kernels first so the profiler's fixed slot lands on kassign
    knorm    <<<KK, 256>>>(cen);
    kwsplit  <<<CC, 256>>>(fw);
    kzero    <<<(BB*KK*CC/4)/256, 256>>>();
    kassign  <<<PP/256, 256>>>(x);
    khist    <<<BB, 256>>>();
    kscan    <<<BB, KK>>>();
    kscatter <<<PP/256, 256>>>();
    ksum     <<<dim3(64, BB), 256>>>(x);
    kdiv     <<<BB*KK, 256>>>();
    kw       <<<dim3(HWD/256, BB), 256>>>(x);
    kconv    <<<dim3(HWD/64, CC/64, BB), 256>>>(x);
    kgemm_mma<<<dim3(CC/64, HWD/128, BB), 256, GEMM_SMEM>>>(fb, out);
}